// round 8
// baseline (speedup 1.0000x reference)
#include <cuda_runtime.h>
#include <cuda_bf16.h>
#include <math.h>
#include <stdint.h>
#include <mma.h>

using namespace nvcuda;

// GCN: out = log_softmax( spmm(adj, relu(spmm(adj, x@W1)+b1) @ W2) + b2 )
// R8: gemm1 software-pipelined: double-buffered smem tiles + register
//     prefetch of the next K-chunk issued before the mma block, one
//     __syncthreads per chunk. Padded strides kept (ALDM=36, BLDM=68).
//     Rest identical to R7 (173us).

#define MAXN 100000
#define MAXE 1600000
#define SCAN_BLK 256
#define ALDM 36
#define BLDM 68

__device__ int   g_off[MAXN];            // counts -> starts -> ends
__device__ int   g_bsum[1024];           // block sums for scan
__device__ int2  g_csr[MAXE];            // (src, val bits)
__device__ float g_support1[(size_t)(MAXN + 128) * 64];  // row-padded for wmma store
__device__ float g_support2[(size_t)MAXN * 16];

static __device__ __forceinline__ float cvt_tf32f(float f) {
    uint32_t r;
    asm("cvt.rna.tf32.f32 %0, %1;" : "=r"(r) : "f"(f));
    return __uint_as_float(r);
}

// ---------------------------------------------------------------- CSR build
__global__ void zero_off_kernel(int N) {
    int i = (blockIdx.x * blockDim.x + threadIdx.x) * 4;
    if (i + 4 <= N) {
        *(int4*)&g_off[i] = make_int4(0, 0, 0, 0);
    } else {
        for (int j = i; j < N; j++) g_off[j] = 0;
    }
}

__global__ void hist_kernel(const int* __restrict__ dst, int E) {
    int i = (blockIdx.x * blockDim.x + threadIdx.x) * 4;
    if (i + 4 <= E) {
        int4 d = *(const int4*)(dst + i);
        atomicAdd(&g_off[d.x], 1);
        atomicAdd(&g_off[d.y], 1);
        atomicAdd(&g_off[d.z], 1);
        atomicAdd(&g_off[d.w], 1);
    } else {
        for (int j = i; j < E; j++) atomicAdd(&g_off[dst[j]], 1);
    }
}

__global__ void scan_a_kernel(int N) {
    __shared__ int ws[8];
    int i = blockIdx.x * SCAN_BLK + threadIdx.x;
    int v = (i < N) ? g_off[i] : 0;
    int lane = threadIdx.x & 31, w = threadIdx.x >> 5;
    int s = v;
    #pragma unroll
    for (int d = 16; d > 0; d >>= 1) s += __shfl_xor_sync(0xFFFFFFFFu, s, d);
    if (lane == 0) ws[w] = s;
    __syncthreads();
    if (threadIdx.x == 0) {
        int t = 0;
        #pragma unroll
        for (int k = 0; k < 8; k++) t += ws[k];
        g_bsum[blockIdx.x] = t;
    }
}

__global__ void scan_b_kernel(int nb) {
    __shared__ int wsum[32];
    int t = threadIdx.x;  // 1024
    int v = (t < nb) ? g_bsum[t] : 0;
    int lane = t & 31, w = t >> 5;
    int incl = v;
    #pragma unroll
    for (int d = 1; d < 32; d <<= 1) {
        int n = __shfl_up_sync(0xFFFFFFFFu, incl, d);
        if (lane >= d) incl += n;
    }
    if (lane == 31) wsum[w] = incl;
    __syncthreads();
    if (w == 0) {
        int s = wsum[lane];
        #pragma unroll
        for (int d = 1; d < 32; d <<= 1) {
            int n = __shfl_up_sync(0xFFFFFFFFu, s, d);
            if (lane >= d) s += n;
        }
        wsum[lane] = s;
    }
    __syncthreads();
    int excl = incl - v + (w ? wsum[w - 1] : 0);
    if (t < nb) g_bsum[t] = excl;
}

__global__ void scan_c_kernel(int N) {
    __shared__ int ws[8];
    int i = blockIdx.x * SCAN_BLK + threadIdx.x;
    int v = (i < N) ? g_off[i] : 0;
    int lane = threadIdx.x & 31, w = threadIdx.x >> 5;
    int incl = v;
    #pragma unroll
    for (int d = 1; d < 32; d <<= 1) {
        int n = __shfl_up_sync(0xFFFFFFFFu, incl, d);
        if (lane >= d) incl += n;
    }
    if (lane == 31) ws[w] = incl;
    __syncthreads();
    if (w == 0 && lane < 8) {
        int s = ws[lane];
        #pragma unroll
        for (int d = 1; d < 8; d <<= 1) {
            int n = __shfl_up_sync(0x000000FFu, s, d);
            if (lane >= d) s += n;
        }
        ws[lane] = s;
    }
    __syncthreads();
    int excl = incl - v + (w ? ws[w - 1] : 0);
    if (i < N) g_off[i] = g_bsum[blockIdx.x] + excl;
}

__global__ void scatter_kernel(const int* __restrict__ src,
                               const int* __restrict__ dst,
                               const float* __restrict__ val, int E) {
    int i = (blockIdx.x * blockDim.x + threadIdx.x) * 4;
    if (i + 4 <= E) {
        int4   s = *(const int4*)(src + i);
        int4   d = *(const int4*)(dst + i);
        float4 v = *(const float4*)(val + i);
        int p0 = atomicAdd(&g_off[d.x], 1);
        int p1 = atomicAdd(&g_off[d.y], 1);
        int p2 = atomicAdd(&g_off[d.z], 1);
        int p3 = atomicAdd(&g_off[d.w], 1);
        g_csr[p0] = make_int2(s.x, __float_as_int(v.x));
        g_csr[p1] = make_int2(s.y, __float_as_int(v.y));
        g_csr[p2] = make_int2(s.z, __float_as_int(v.z));
        g_csr[p3] = make_int2(s.w, __float_as_int(v.w));
    } else {
        for (int j = i; j < E; j++) {
            int p = atomicAdd(&g_off[dst[j]], 1);
            g_csr[p] = make_int2(src[j], __float_as_int(val[j]));
        }
    }
}

// ---------------------------------------------------------------- GEMM1 (wmma tf32)
// support1[N,64] = x[N,256] @ W1[256,64].
// CTA: 128 threads (4 warps), 128x64 tile, warp = 32 rows (acc[2][4]).
// K: 8 chunks of 32, double-buffered smem + register prefetch pipeline.
__global__ void __launch_bounds__(128, 2)
gemm1_wmma_kernel(const float* __restrict__ x, const float* __restrict__ W1,
                  int N) {
    __shared__ float As[2][128 * ALDM];   // 2 x 18KB
    __shared__ float Bs[2][32 * BLDM];    // 2 x 8.5KB

    int tid = threadIdx.x, wid = tid >> 5;
    int m0 = blockIdx.x * 128;

    // per-thread load coordinates
    int arow = tid >> 3;               // 0..15 base row group (x8 rows)
    int ac4 = (tid & 7) << 2;          // A col (float4)
    int brow = tid >> 4;               // 0..7 base row group (x4 rows)
    int bc4 = (tid & 15) << 2;         // B col (float4)

    wmma::fragment<wmma::accumulator, 16, 16, 8, float> acc[2][4];
    #pragma unroll
    for (int i = 0; i < 2; i++)
        #pragma unroll
        for (int nt = 0; nt < 4; nt++) wmma::fill_fragment(acc[i][nt], 0.0f);

    float4 pa[8];   // A prefetch: 8 rows/thread
    float4 pb[4];   // B prefetch: 4 rows/thread

    // ---- prologue: load chunk 0 into regs, store to buf 0
    #pragma unroll
    for (int j = 0; j < 8; j++) {
        int row = arow + (j << 4);
        int gr = m0 + row;
        pa[j] = make_float4(0.f, 0.f, 0.f, 0.f);
        if (gr < N) pa[j] = *(const float4*)(x + (size_t)gr * 256 + ac4);
    }
    #pragma unroll
    for (int j = 0; j < 4; j++) {
        int row = brow + (j << 3);
        pb[j] = *(const float4*)(W1 + (size_t)row * 64 + bc4);
    }
    #pragma unroll
    for (int j = 0; j < 8; j++) {
        int row = arow + (j << 4);
        *(float4*)&As[0][row * ALDM + ac4] =
            make_float4(cvt_tf32f(pa[j].x), cvt_tf32f(pa[j].y),
                        cvt_tf32f(pa[j].z), cvt_tf32f(pa[j].w));
    }
    #pragma unroll
    for (int j = 0; j < 4; j++) {
        int row = brow + (j << 3);
        *(float4*)&Bs[0][row * BLDM + bc4] =
            make_float4(cvt_tf32f(pb[j].x), cvt_tf32f(pb[j].y),
                        cvt_tf32f(pb[j].z), cvt_tf32f(pb[j].w));
    }
    __syncthreads();

    #pragma unroll
    for (int ch = 0; ch < 8; ch++) {
        int p = ch & 1;
        // prefetch next chunk (LDGs issue before the mma block; latency
        // hidden behind the 32-mma chain)
        if (ch < 7) {
            int k0 = (ch + 1) << 5;
            #pragma unroll
            for (int j = 0; j < 8; j++) {
                int row = arow + (j << 4);
                int gr = m0 + row;
                pa[j] = make_float4(0.f, 0.f, 0.f, 0.f);
                if (gr < N)
                    pa[j] = *(const float4*)(x + (size_t)gr * 256 + k0 + ac4);
            }
            #pragma unroll
            for (int j = 0; j < 4; j++) {
                int row = brow + (j << 3);
                pb[j] = *(const float4*)(W1 + (size_t)(k0 + row) * 64 + bc4);
            }
        }

        #pragma unroll
        for (int kk = 0; kk < 4; kk++) {
            wmma::fragment<wmma::matrix_a, 16, 16, 8, wmma::precision::tf32,
                           wmma::row_major> a0, a1;
            wmma::load_matrix_sync(a0, &As[p][(wid * 32) * ALDM + kk * 8], ALDM);
            wmma::load_matrix_sync(a1, &As[p][(wid * 32 + 16) * ALDM + kk * 8], ALDM);
            #pragma unroll
            for (int nt = 0; nt < 4; nt++) {
                wmma::fragment<wmma::matrix_b, 16, 16, 8, wmma::precision::tf32,
                               wmma::row_major> b_frag;
                wmma::load_matrix_sync(b_frag, &Bs[p][(kk * 8) * BLDM + nt * 16], BLDM);
                wmma::mma_sync(acc[0][nt], a0, b_frag, acc[0][nt]);
                wmma::mma_sync(acc[1][nt], a1, b_frag, acc[1][nt]);
            }
        }

        if (ch < 7) {
            int q = p ^ 1;   // other buffer: last read finished before prev sync
            #pragma unroll
            for (int j = 0; j < 8; j++) {
                int row = arow + (j << 4);
                *(float4*)&As[q][row * ALDM + ac4] =
                    make_float4(cvt_tf32f(pa[j].x), cvt_tf32f(pa[j].y),
                                cvt_tf32f(pa[j].z), cvt_tf32f(pa[j].w));
            }
            #pragma unroll
            for (int j = 0; j < 4; j++) {
                int row = brow + (j << 3);
                *(float4*)&Bs[q][row * BLDM + bc4] =
                    make_float4(cvt_tf32f(pb[j].x), cvt_tf32f(pb[j].y),
                                cvt_tf32f(pb[j].z), cvt_tf32f(pb[j].w));
            }
        }
        __syncthreads();
    }

    // Direct global store; rows beyond N land in the padded tail (harmless).
    #pragma unroll
    for (int i = 0; i < 2; i++) {
        int r0 = m0 + wid * 32 + i * 16;
        #pragma unroll
        for (int nt = 0; nt < 4; nt++)
            wmma::store_matrix_sync(&g_support1[(size_t)r0 * 64 + nt * 16],
                                    acc[i][nt], 64, wmma::mem_row_major);
    }
}

// ---------------------------------------- spMM1 + (relu,b1) + GEMM2 fused
__global__ void spmm1_gemm2_kernel(const float* __restrict__ b1,
                                   const float* __restrict__ W2, int N) {
    __shared__ float w2t[16][68];   // transposed W2, padded
    int tid = threadIdx.x;          // 256
    for (int i = tid; i < 64 * 16; i += 256) {
        int k = i >> 4, j = i & 15;
        w2t[j][k] = W2[i];
    }
    __syncthreads();

    int t = blockIdx.x * 256 + tid;
    int node = t >> 4;
    int c = (t & 15) << 2;
    bool valid = (node < N);

    float4 acc = make_float4(0.f, 0.f, 0.f, 0.f);
    if (valid) {
        int start = node ? g_off[node - 1] : 0;
        int end = g_off[node];
        int e = start;
        for (; e + 4 <= end; e += 4) {
            int2 e0 = g_csr[e], e1 = g_csr[e + 1], e2 = g_csr[e + 2], e3 = g_csr[e + 3];
            float4 v0 = *(const float4*)&g_support1[(size_t)e0.x * 64 + c];
            float4 v1 = *(const float4*)&g_support1[(size_t)e1.x * 64 + c];
            float4 v2 = *(const float4*)&g_support1[(size_t)e2.x * 64 + c];
            float4 v3 = *(const float4*)&g_support1[(size_t)e3.x * 64 + c];
            float w0 = __int_as_float(e0.y), w1 = __int_as_float(e1.y);
            float w2 = __int_as_float(e2.y), w3 = __int_as_float(e3.y);
            acc.x = fmaf(w0, v0.x, acc.x); acc.y = fmaf(w0, v0.y, acc.y);
            acc.z = fmaf(w0, v0.z, acc.z); acc.w = fmaf(w0, v0.w, acc.w);
            acc.x = fmaf(w1, v1.x, acc.x); acc.y = fmaf(w1, v1.y, acc.y);
            acc.z = fmaf(w1, v1.z, acc.z); acc.w = fmaf(w1, v1.w, acc.w);
            acc.x = fmaf(w2, v2.x, acc.x); acc.y = fmaf(w2, v2.y, acc.y);
            acc.z = fmaf(w2, v2.z, acc.z); acc.w = fmaf(w2, v2.w, acc.w);
            acc.x = fmaf(w3, v3.x, acc.x); acc.y = fmaf(w3, v3.y, acc.y);
            acc.z = fmaf(w3, v3.z, acc.z); acc.w = fmaf(w3, v3.w, acc.w);
        }
        for (; e < end; e++) {
            int2 ed = g_csr[e];
            float w = __int_as_float(ed.y);
            float4 v = *(const float4*)&g_support1[(size_t)ed.x * 64 + c];
            acc.x = fmaf(w, v.x, acc.x); acc.y = fmaf(w, v.y, acc.y);
            acc.z = fmaf(w, v.z, acc.z); acc.w = fmaf(w, v.w, acc.w);
        }
        float4 bb = *(const float4*)&b1[c];
        acc.x = fmaxf(acc.x + bb.x, 0.f);
        acc.y = fmaxf(acc.y + bb.y, 0.f);
        acc.z = fmaxf(acc.z + bb.z, 0.f);
        acc.w = fmaxf(acc.w + bb.w, 0.f);
    }

    float part[16];
    #pragma unroll
    for (int j = 0; j < 16; j++) {
        float s = acc.x * w2t[j][c];
        s = fmaf(acc.y, w2t[j][c + 1], s);
        s = fmaf(acc.z, w2t[j][c + 2], s);
        s = fmaf(acc.w, w2t[j][c + 3], s);
        part[j] = s;
    }
    #pragma unroll
    for (int d = 1; d < 16; d <<= 1) {
        #pragma unroll
        for (int j = 0; j < 16; j++)
            part[j] += __shfl_xor_sync(0xFFFFFFFFu, part[j], d);
    }
    int sub = t & 15;
    if (valid && sub < 4) {
        *(float4*)&g_support2[(size_t)node * 16 + sub * 4] =
            make_float4(part[sub * 4], part[sub * 4 + 1],
                        part[sub * 4 + 2], part[sub * 4 + 3]);
    }
}

// ------------------------------------------------ spMM2 + log_softmax fused
__global__ void spmm2_kernel(const float* __restrict__ b2,
                             float* __restrict__ out, int N) {
    int t = blockIdx.x * blockDim.x + threadIdx.x;
    int node = t >> 2;
    int q = (t & 3) << 2;

    float4 acc = make_float4(0.f, 0.f, 0.f, 0.f);
    if (node < N) {
        int start = node ? g_off[node - 1] : 0;
        int end = g_off[node];
        int e = start;
        for (; e + 4 <= end; e += 4) {
            int2 e0 = g_csr[e], e1 = g_csr[e + 1], e2 = g_csr[e + 2], e3 = g_csr[e + 3];
            float4 v0 = *(const float4*)&g_support2[(size_t)e0.x * 16 + q];
            float4 v1 = *(const float4*)&g_support2[(size_t)e1.x * 16 + q];
            float4 v2 = *(const float4*)&g_support2[(size_t)e2.x * 16 + q];
            float4 v3 = *(const float4*)&g_support2[(size_t)e3.x * 16 + q];
            float w0 = __int_as_float(e0.y), w1 = __int_as_float(e1.y);
            float w2 = __int_as_float(e2.y), w3 = __int_as_float(e3.y);
            acc.x = fmaf(w0, v0.x, acc.x); acc.y = fmaf(w0, v0.y, acc.y);
            acc.z = fmaf(w0, v0.z, acc.z); acc.w = fmaf(w0, v0.w, acc.w);
            acc.x = fmaf(w1, v1.x, acc.x); acc.y = fmaf(w1, v1.y, acc.y);
            acc.z = fmaf(w1, v1.z, acc.z); acc.w = fmaf(w1, v1.w, acc.w);
            acc.x = fmaf(w2, v2.x, acc.x); acc.y = fmaf(w2, v2.y, acc.y);
            acc.z = fmaf(w2, v2.z, acc.z); acc.w = fmaf(w2, v2.w, acc.w);
            acc.x = fmaf(w3, v3.x, acc.x); acc.y = fmaf(w3, v3.y, acc.y);
            acc.z = fmaf(w3, v3.z, acc.z); acc.w = fmaf(w3, v3.w, acc.w);
        }
        for (; e < end; e++) {
            int2 ed = g_csr[e];
            float w = __int_as_float(ed.y);
            float4 v = *(const float4*)&g_support2[(size_t)ed.x * 16 + q];
            acc.x = fmaf(w, v.x, acc.x); acc.y = fmaf(w, v.y, acc.y);
            acc.z = fmaf(w, v.z, acc.z); acc.w = fmaf(w, v.w, acc.w);
        }
        float4 bb = *(const float4*)&b2[q];
        acc.x += bb.x; acc.y += bb.y; acc.z += bb.z; acc.w += bb.w;
    }

    float m = fmaxf(fmaxf(acc.x, acc.y), fmaxf(acc.z, acc.w));
    m = fmaxf(m, __shfl_xor_sync(0xFFFFFFFFu, m, 1));
    m = fmaxf(m, __shfl_xor_sync(0xFFFFFFFFu, m, 2));
    float s = expf(acc.x - m) + expf(acc.y - m) + expf(acc.z - m) + expf(acc.w - m);
    s += __shfl_xor_sync(0xFFFFFFFFu, s, 1);
    s += __shfl_xor_sync(0xFFFFFFFFu, s, 2);
    float lse = m + logf(s);

    if (node < N) {
        *(float4*)&out[(size_t)node * 16 + q] =
            make_float4(acc.x - lse, acc.y - lse, acc.z - lse, acc.w - lse);
    }
}

// ---------------------------------------------------------------- launch
extern "C" void kernel_launch(void* const* d_in, const int* in_sizes, int n_in,
                              void* d_out, int out_size) {
    const float* x    = (const float*)d_in[0];
    const int*   esrc = (const int*)d_in[1];
    const int*   edst = (const int*)d_in[2];
    const float* ev   = (const float*)d_in[3];
    const float* W1   = (const float*)d_in[4];
    const float* b1   = (const float*)d_in[5];
    const float* W2   = (const float*)d_in[6];
    const float* b2   = (const float*)d_in[7];
    float* out = (float*)d_out;

    int E = in_sizes[1];
    int N = in_sizes[0] / 256;

    int eq = (E + 3) / 4;
    int nq = (N + 3) / 4;
    int nb = (N + SCAN_BLK - 1) / SCAN_BLK;

    // CSR build (gemm1 slotted at launch index 3 so ncu profiles it)
    zero_off_kernel<<<(nq + 255) / 256, 256>>>(N);                 // 0
    hist_kernel<<<(eq + 255) / 256, 256>>>(edst, E);               // 1
    scan_a_kernel<<<nb, SCAN_BLK>>>(N);                            // 2
    gemm1_wmma_kernel<<<(N + 127) / 128, 128>>>(x, W1, N);         // 3 <- profiled
    scan_b_kernel<<<1, 1024>>>(nb);                                // 4
    scan_c_kernel<<<nb, SCAN_BLK>>>(N);                            // 5
    scatter_kernel<<<(eq + 255) / 256, 256>>>(esrc, edst, ev, E);  // 6

    // Layer 1 + gemm2 fused
    spmm1_gemm2_kernel<<<(N * 16 + 255) / 256, 256>>>(b1, W2, N);  // 7

    // Layer 2 + log_softmax
    spmm2_kernel<<<(N * 4 + 255) / 256, 256>>>(b2, out, N);        // 8
}

// round 9
// speedup vs baseline: 1.2134x; 1.2134x over previous
#include <cuda_runtime.h>
#include <cuda_bf16.h>
#include <math.h>
#include <stdint.h>
#include <mma.h>

using namespace nvcuda;

// GCN: out = log_softmax( spmm(adj, relu(spmm(adj, x@W1)+b1) @ W2) + b2 )
// R9: gemm1 pipelined via cp.async (LDGSTS) double-buffered smem — no
//     register staging (R8's 255-reg blowup reverted). tf32 rounding now
//     RZ (mma-internal truncation) instead of cvt.rna. Rest = R7 (173us).

#define MAXN 100000
#define MAXE 1600000
#define SCAN_BLK 256
#define ALDM 36
#define BLDM 68

__device__ int   g_off[MAXN];            // counts -> starts -> ends
__device__ int   g_bsum[1024];           // block sums for scan
__device__ int2  g_csr[MAXE];            // (src, val bits)
__device__ float g_support1[(size_t)(MAXN + 128) * 64];  // row-padded for wmma store
__device__ float g_support2[(size_t)MAXN * 16];

static __device__ __forceinline__ void cp_async16(uint32_t dst_smem,
                                                  const void* src,
                                                  int src_bytes) {
    asm volatile("cp.async.cg.shared.global [%0], [%1], 16, %2;"
                 :: "r"(dst_smem), "l"(src), "r"(src_bytes) : "memory");
}
#define CP_COMMIT() asm volatile("cp.async.commit_group;" ::: "memory")
#define CP_WAIT(n)  asm volatile("cp.async.wait_group %0;" :: "n"(n) : "memory")

// ---------------------------------------------------------------- CSR build
__global__ void zero_off_kernel(int N) {
    int i = (blockIdx.x * blockDim.x + threadIdx.x) * 4;
    if (i + 4 <= N) {
        *(int4*)&g_off[i] = make_int4(0, 0, 0, 0);
    } else {
        for (int j = i; j < N; j++) g_off[j] = 0;
    }
}

__global__ void hist_kernel(const int* __restrict__ dst, int E) {
    int i = (blockIdx.x * blockDim.x + threadIdx.x) * 4;
    if (i + 4 <= E) {
        int4 d = *(const int4*)(dst + i);
        atomicAdd(&g_off[d.x], 1);
        atomicAdd(&g_off[d.y], 1);
        atomicAdd(&g_off[d.z], 1);
        atomicAdd(&g_off[d.w], 1);
    } else {
        for (int j = i; j < E; j++) atomicAdd(&g_off[dst[j]], 1);
    }
}

__global__ void scan_a_kernel(int N) {
    __shared__ int ws[8];
    int i = blockIdx.x * SCAN_BLK + threadIdx.x;
    int v = (i < N) ? g_off[i] : 0;
    int lane = threadIdx.x & 31, w = threadIdx.x >> 5;
    int s = v;
    #pragma unroll
    for (int d = 16; d > 0; d >>= 1) s += __shfl_xor_sync(0xFFFFFFFFu, s, d);
    if (lane == 0) ws[w] = s;
    __syncthreads();
    if (threadIdx.x == 0) {
        int t = 0;
        #pragma unroll
        for (int k = 0; k < 8; k++) t += ws[k];
        g_bsum[blockIdx.x] = t;
    }
}

__global__ void scan_b_kernel(int nb) {
    __shared__ int wsum[32];
    int t = threadIdx.x;  // 1024
    int v = (t < nb) ? g_bsum[t] : 0;
    int lane = t & 31, w = t >> 5;
    int incl = v;
    #pragma unroll
    for (int d = 1; d < 32; d <<= 1) {
        int n = __shfl_up_sync(0xFFFFFFFFu, incl, d);
        if (lane >= d) incl += n;
    }
    if (lane == 31) wsum[w] = incl;
    __syncthreads();
    if (w == 0) {
        int s = wsum[lane];
        #pragma unroll
        for (int d = 1; d < 32; d <<= 1) {
            int n = __shfl_up_sync(0xFFFFFFFFu, s, d);
            if (lane >= d) s += n;
        }
        wsum[lane] = s;
    }
    __syncthreads();
    int excl = incl - v + (w ? wsum[w - 1] : 0);
    if (t < nb) g_bsum[t] = excl;
}

__global__ void scan_c_kernel(int N) {
    __shared__ int ws[8];
    int i = blockIdx.x * SCAN_BLK + threadIdx.x;
    int v = (i < N) ? g_off[i] : 0;
    int lane = threadIdx.x & 31, w = threadIdx.x >> 5;
    int incl = v;
    #pragma unroll
    for (int d = 1; d < 32; d <<= 1) {
        int n = __shfl_up_sync(0xFFFFFFFFu, incl, d);
        if (lane >= d) incl += n;
    }
    if (lane == 31) ws[w] = incl;
    __syncthreads();
    if (w == 0 && lane < 8) {
        int s = ws[lane];
        #pragma unroll
        for (int d = 1; d < 8; d <<= 1) {
            int n = __shfl_up_sync(0x000000FFu, s, d);
            if (lane >= d) s += n;
        }
        ws[lane] = s;
    }
    __syncthreads();
    int excl = incl - v + (w ? ws[w - 1] : 0);
    if (i < N) g_off[i] = g_bsum[blockIdx.x] + excl;
}

__global__ void scatter_kernel(const int* __restrict__ src,
                               const int* __restrict__ dst,
                               const float* __restrict__ val, int E) {
    int i = (blockIdx.x * blockDim.x + threadIdx.x) * 4;
    if (i + 4 <= E) {
        int4   s = *(const int4*)(src + i);
        int4   d = *(const int4*)(dst + i);
        float4 v = *(const float4*)(val + i);
        int p0 = atomicAdd(&g_off[d.x], 1);
        int p1 = atomicAdd(&g_off[d.y], 1);
        int p2 = atomicAdd(&g_off[d.z], 1);
        int p3 = atomicAdd(&g_off[d.w], 1);
        g_csr[p0] = make_int2(s.x, __float_as_int(v.x));
        g_csr[p1] = make_int2(s.y, __float_as_int(v.y));
        g_csr[p2] = make_int2(s.z, __float_as_int(v.z));
        g_csr[p3] = make_int2(s.w, __float_as_int(v.w));
    } else {
        for (int j = i; j < E; j++) {
            int p = atomicAdd(&g_off[dst[j]], 1);
            g_csr[p] = make_int2(src[j], __float_as_int(val[j]));
        }
    }
}

// ---------------------------------------------------------------- GEMM1 (wmma tf32)
// support1[N,64] = x[N,256] @ W1[256,64].
// CTA: 128 threads (4 warps), 128x64 tile, warp = 32 rows (acc[2][4]).
// K: 8 chunks of 32, double-buffered smem filled by cp.async (no register
// staging). tf32 rounding = RZ (mma truncates fp32 inputs).
__global__ void __launch_bounds__(128, 3)
gemm1_wmma_kernel(const float* __restrict__ x, const float* __restrict__ W1,
                  int N) {
    __shared__ float As[2][128 * ALDM];   // 2 x 18KB
    __shared__ float Bs[2][32 * BLDM];    // 2 x 8.5KB

    int tid = threadIdx.x, wid = tid >> 5;
    int m0 = blockIdx.x * 128;

    // per-thread cp.async coordinates
    int arow = tid >> 3;               // 0..15 (+ j*16, j<8)
    int ac4 = (tid & 7) << 2;          // A col (float)
    int brow = tid >> 4;               // 0..7 (+ j*8, j<4)
    int bc4 = (tid & 15) << 2;         // B col (float)

    wmma::fragment<wmma::accumulator, 16, 16, 8, float> acc[2][4];
    #pragma unroll
    for (int i = 0; i < 2; i++)
        #pragma unroll
        for (int nt = 0; nt < 4; nt++) wmma::fill_fragment(acc[i][nt], 0.0f);

    // issue one K-chunk's copies into buffer `buf`
    auto issue = [&](int ch, int buf) {
        int k0 = ch << 5;
        #pragma unroll
        for (int j = 0; j < 8; j++) {
            int row = arow + (j << 4);
            int gr = m0 + row;
            bool ok = (gr < N);
            const float* src = x + (size_t)(ok ? gr : 0) * 256 + k0 + ac4;
            uint32_t dst = (uint32_t)__cvta_generic_to_shared(
                &As[buf][row * ALDM + ac4]);
            cp_async16(dst, src, ok ? 16 : 0);
        }
        #pragma unroll
        for (int j = 0; j < 4; j++) {
            int row = brow + (j << 3);
            const float* src = W1 + (size_t)(k0 + row) * 64 + bc4;
            uint32_t dst = (uint32_t)__cvta_generic_to_shared(
                &Bs[buf][row * BLDM + bc4]);
            cp_async16(dst, src, 16);
        }
        CP_COMMIT();
    };

    issue(0, 0);

    #pragma unroll
    for (int ch = 0; ch < 8; ch++) {
        int p = ch & 1;
        if (ch < 7) {
            issue(ch + 1, p ^ 1);
            CP_WAIT(1);
        } else {
            CP_WAIT(0);
        }
        __syncthreads();

        #pragma unroll
        for (int kk = 0; kk < 4; kk++) {
            wmma::fragment<wmma::matrix_a, 16, 16, 8, wmma::precision::tf32,
                           wmma::row_major> a0, a1;
            wmma::load_matrix_sync(a0, &As[p][(wid * 32) * ALDM + kk * 8], ALDM);
            wmma::load_matrix_sync(a1, &As[p][(wid * 32 + 16) * ALDM + kk * 8], ALDM);
            #pragma unroll
            for (int nt = 0; nt < 4; nt++) {
                wmma::fragment<wmma::matrix_b, 16, 16, 8, wmma::precision::tf32,
                               wmma::row_major> b_frag;
                wmma::load_matrix_sync(b_frag, &Bs[p][(kk * 8) * BLDM + nt * 16], BLDM);
                wmma::mma_sync(acc[0][nt], a0, b_frag, acc[0][nt]);
                wmma::mma_sync(acc[1][nt], a1, b_frag, acc[1][nt]);
            }
        }
        __syncthreads();   // all warps done reading buf p before it is refilled
    }

    // Direct global store; rows beyond N land in the padded tail (harmless).
    #pragma unroll
    for (int i = 0; i < 2; i++) {
        int r0 = m0 + wid * 32 + i * 16;
        #pragma unroll
        for (int nt = 0; nt < 4; nt++)
            wmma::store_matrix_sync(&g_support1[(size_t)r0 * 64 + nt * 16],
                                    acc[i][nt], 64, wmma::mem_row_major);
    }
}

// ---------------------------------------- spMM1 + (relu,b1) + GEMM2 fused
__global__ void spmm1_gemm2_kernel(const float* __restrict__ b1,
                                   const float* __restrict__ W2, int N) {
    __shared__ float w2t[16][68];   // transposed W2, padded
    int tid = threadIdx.x;          // 256
    for (int i = tid; i < 64 * 16; i += 256) {
        int k = i >> 4, j = i & 15;
        w2t[j][k] = W2[i];
    }
    __syncthreads();

    int t = blockIdx.x * 256 + tid;
    int node = t >> 4;
    int c = (t & 15) << 2;
    bool valid = (node < N);

    float4 acc = make_float4(0.f, 0.f, 0.f, 0.f);
    if (valid) {
        int start = node ? g_off[node - 1] : 0;
        int end = g_off[node];
        int e = start;
        for (; e + 4 <= end; e += 4) {
            int2 e0 = g_csr[e], e1 = g_csr[e + 1], e2 = g_csr[e + 2], e3 = g_csr[e + 3];
            float4 v0 = *(const float4*)&g_support1[(size_t)e0.x * 64 + c];
            float4 v1 = *(const float4*)&g_support1[(size_t)e1.x * 64 + c];
            float4 v2 = *(const float4*)&g_support1[(size_t)e2.x * 64 + c];
            float4 v3 = *(const float4*)&g_support1[(size_t)e3.x * 64 + c];
            float w0 = __int_as_float(e0.y), w1 = __int_as_float(e1.y);
            float w2 = __int_as_float(e2.y), w3 = __int_as_float(e3.y);
            acc.x = fmaf(w0, v0.x, acc.x); acc.y = fmaf(w0, v0.y, acc.y);
            acc.z = fmaf(w0, v0.z, acc.z); acc.w = fmaf(w0, v0.w, acc.w);
            acc.x = fmaf(w1, v1.x, acc.x); acc.y = fmaf(w1, v1.y, acc.y);
            acc.z = fmaf(w1, v1.z, acc.z); acc.w = fmaf(w1, v1.w, acc.w);
            acc.x = fmaf(w2, v2.x, acc.x); acc.y = fmaf(w2, v2.y, acc.y);
            acc.z = fmaf(w2, v2.z, acc.z); acc.w = fmaf(w2, v2.w, acc.w);
            acc.x = fmaf(w3, v3.x, acc.x); acc.y = fmaf(w3, v3.y, acc.y);
            acc.z = fmaf(w3, v3.z, acc.z); acc.w = fmaf(w3, v3.w, acc.w);
        }
        for (; e < end; e++) {
            int2 ed = g_csr[e];
            float w = __int_as_float(ed.y);
            float4 v = *(const float4*)&g_support1[(size_t)ed.x * 64 + c];
            acc.x = fmaf(w, v.x, acc.x); acc.y = fmaf(w, v.y, acc.y);
            acc.z = fmaf(w, v.z, acc.z); acc.w = fmaf(w, v.w, acc.w);
        }
        float4 bb = *(const float4*)&b1[c];
        acc.x = fmaxf(acc.x + bb.x, 0.f);
        acc.y = fmaxf(acc.y + bb.y, 0.f);
        acc.z = fmaxf(acc.z + bb.z, 0.f);
        acc.w = fmaxf(acc.w + bb.w, 0.f);
    }

    float part[16];
    #pragma unroll
    for (int j = 0; j < 16; j++) {
        float s = acc.x * w2t[j][c];
        s = fmaf(acc.y, w2t[j][c + 1], s);
        s = fmaf(acc.z, w2t[j][c + 2], s);
        s = fmaf(acc.w, w2t[j][c + 3], s);
        part[j] = s;
    }
    #pragma unroll
    for (int d = 1; d < 16; d <<= 1) {
        #pragma unroll
        for (int j = 0; j < 16; j++)
            part[j] += __shfl_xor_sync(0xFFFFFFFFu, part[j], d);
    }
    int sub = t & 15;
    if (valid && sub < 4) {
        *(float4*)&g_support2[(size_t)node * 16 + sub * 4] =
            make_float4(part[sub * 4], part[sub * 4 + 1],
                        part[sub * 4 + 2], part[sub * 4 + 3]);
    }
}

// ------------------------------------------------ spMM2 + log_softmax fused
__global__ void spmm2_kernel(const float* __restrict__ b2,
                             float* __restrict__ out, int N) {
    int t = blockIdx.x * blockDim.x + threadIdx.x;
    int node = t >> 2;
    int q = (t & 3) << 2;

    float4 acc = make_float4(0.f, 0.f, 0.f, 0.f);
    if (node < N) {
        int start = node ? g_off[node - 1] : 0;
        int end = g_off[node];
        int e = start;
        for (; e + 4 <= end; e += 4) {
            int2 e0 = g_csr[e], e1 = g_csr[e + 1], e2 = g_csr[e + 2], e3 = g_csr[e + 3];
            float4 v0 = *(const float4*)&g_support2[(size_t)e0.x * 16 + q];
            float4 v1 = *(const float4*)&g_support2[(size_t)e1.x * 16 + q];
            float4 v2 = *(const float4*)&g_support2[(size_t)e2.x * 16 + q];
            float4 v3 = *(const float4*)&g_support2[(size_t)e3.x * 16 + q];
            float w0 = __int_as_float(e0.y), w1 = __int_as_float(e1.y);
            float w2 = __int_as_float(e2.y), w3 = __int_as_float(e3.y);
            acc.x = fmaf(w0, v0.x, acc.x); acc.y = fmaf(w0, v0.y, acc.y);
            acc.z = fmaf(w0, v0.z, acc.z); acc.w = fmaf(w0, v0.w, acc.w);
            acc.x = fmaf(w1, v1.x, acc.x); acc.y = fmaf(w1, v1.y, acc.y);
            acc.z = fmaf(w1, v1.z, acc.z); acc.w = fmaf(w1, v1.w, acc.w);
            acc.x = fmaf(w2, v2.x, acc.x); acc.y = fmaf(w2, v2.y, acc.y);
            acc.z = fmaf(w2, v2.z, acc.z); acc.w = fmaf(w2, v2.w, acc.w);
            acc.x = fmaf(w3, v3.x, acc.x); acc.y = fmaf(w3, v3.y, acc.y);
            acc.z = fmaf(w3, v3.z, acc.z); acc.w = fmaf(w3, v3.w, acc.w);
        }
        for (; e < end; e++) {
            int2 ed = g_csr[e];
            float w = __int_as_float(ed.y);
            float4 v = *(const float4*)&g_support2[(size_t)ed.x * 16 + q];
            acc.x = fmaf(w, v.x, acc.x); acc.y = fmaf(w, v.y, acc.y);
            acc.z = fmaf(w, v.z, acc.z); acc.w = fmaf(w, v.w, acc.w);
        }
        float4 bb = *(const float4*)&b2[q];
        acc.x += bb.x; acc.y += bb.y; acc.z += bb.z; acc.w += bb.w;
    }

    float m = fmaxf(fmaxf(acc.x, acc.y), fmaxf(acc.z, acc.w));
    m = fmaxf(m, __shfl_xor_sync(0xFFFFFFFFu, m, 1));
    m = fmaxf(m, __shfl_xor_sync(0xFFFFFFFFu, m, 2));
    float s = expf(acc.x - m) + expf(acc.y - m) + expf(acc.z - m) + expf(acc.w - m);
    s += __shfl_xor_sync(0xFFFFFFFFu, s, 1);
    s += __shfl_xor_sync(0xFFFFFFFFu, s, 2);
    float lse = m + logf(s);

    if (node < N) {
        *(float4*)&out[(size_t)node * 16 + q] =
            make_float4(acc.x - lse, acc.y - lse, acc.z - lse, acc.w - lse);
    }
}

// ---------------------------------------------------------------- launch
extern "C" void kernel_launch(void* const* d_in, const int* in_sizes, int n_in,
                              void* d_out, int out_size) {
    const float* x    = (const float*)d_in[0];
    const int*   esrc = (const int*)d_in[1];
    const int*   edst = (const int*)d_in[2];
    const float* ev   = (const float*)d_in[3];
    const float* W1   = (const float*)d_in[4];
    const float* b1   = (const float*)d_in[5];
    const float* W2   = (const float*)d_in[6];
    const float* b2   = (const float*)d_in[7];
    float* out = (float*)d_out;

    int E = in_sizes[1];
    int N = in_sizes[0] / 256;

    int eq = (E + 3) / 4;
    int nq = (N + 3) / 4;
    int nb = (N + SCAN_BLK - 1) / SCAN_BLK;

    // CSR build (gemm1 slotted at launch index 3 so ncu profiles it)
    zero_off_kernel<<<(nq + 255) / 256, 256>>>(N);                 // 0
    hist_kernel<<<(eq + 255) / 256, 256>>>(edst, E);               // 1
    scan_a_kernel<<<nb, SCAN_BLK>>>(N);                            // 2
    gemm1_wmma_kernel<<<(N + 127) / 128, 128>>>(x, W1, N);         // 3 <- profiled
    scan_b_kernel<<<1, 1024>>>(nb);                                // 4
    scan_c_kernel<<<nb, SCAN_BLK>>>(N);                            // 5
    scatter_kernel<<<(eq + 255) / 256, 256>>>(esrc, edst, ev, E);  // 6

    // Layer 1 + gemm2 fused
    spmm1_gemm2_kernel<<<(N * 16 + 255) / 256, 256>>>(b1, W2, N);  // 7

    // Layer 2 + log_softmax
    spmm2_kernel<<<(N * 4 + 255) / 256, 256>>>(b2, out, N);        // 8
}

// round 10
// speedup vs baseline: 1.3600x; 1.1208x over previous
#include <cuda_runtime.h>
#include <cuda_bf16.h>
#include <math.h>
#include <stdint.h>
#include <mma.h>

using namespace nvcuda;

// GCN: out = log_softmax( spmm(adj, relu(spmm(adj, x@W1)+b1) @ W2) + b2 )
// R10: (a) gemm1 reverted to R7 RNA/register version (R9's RZ truncation
//      left only 1.5x margin to the 1e-3 gate). (b) CSR build chain forked
//      onto a side stream, overlapped with gemm1 (disjoint pipes: LTS+atomics
//      vs tensor+LDS), joined before spmm1_gemm2.

#define MAXN 100000
#define MAXE 1600000
#define SCAN_BLK 256
#define ALDM 36
#define BLDM 68

__device__ int   g_off[MAXN];            // counts -> starts -> ends
__device__ int   g_bsum[1024];           // block sums for scan
__device__ int2  g_csr[MAXE];            // (src, val bits)
__device__ float g_support1[(size_t)(MAXN + 128) * 64];  // row-padded for wmma store
__device__ float g_support2[(size_t)MAXN * 16];

static __device__ __forceinline__ float cvt_tf32f(float f) {
    uint32_t r;
    asm("cvt.rna.tf32.f32 %0, %1;" : "=r"(r) : "f"(f));
    return __uint_as_float(r);
}

// ---------------------------------------------------------------- CSR build
__global__ void zero_off_kernel(int N) {
    int i = (blockIdx.x * blockDim.x + threadIdx.x) * 4;
    if (i + 4 <= N) {
        *(int4*)&g_off[i] = make_int4(0, 0, 0, 0);
    } else {
        for (int j = i; j < N; j++) g_off[j] = 0;
    }
}

__global__ void hist_kernel(const int* __restrict__ dst, int E) {
    int i = (blockIdx.x * blockDim.x + threadIdx.x) * 4;
    if (i + 4 <= E) {
        int4 d = *(const int4*)(dst + i);
        atomicAdd(&g_off[d.x], 1);
        atomicAdd(&g_off[d.y], 1);
        atomicAdd(&g_off[d.z], 1);
        atomicAdd(&g_off[d.w], 1);
    } else {
        for (int j = i; j < E; j++) atomicAdd(&g_off[dst[j]], 1);
    }
}

__global__ void scan_a_kernel(int N) {
    __shared__ int ws[8];
    int i = blockIdx.x * SCAN_BLK + threadIdx.x;
    int v = (i < N) ? g_off[i] : 0;
    int lane = threadIdx.x & 31, w = threadIdx.x >> 5;
    int s = v;
    #pragma unroll
    for (int d = 16; d > 0; d >>= 1) s += __shfl_xor_sync(0xFFFFFFFFu, s, d);
    if (lane == 0) ws[w] = s;
    __syncthreads();
    if (threadIdx.x == 0) {
        int t = 0;
        #pragma unroll
        for (int k = 0; k < 8; k++) t += ws[k];
        g_bsum[blockIdx.x] = t;
    }
}

__global__ void scan_b_kernel(int nb) {
    __shared__ int wsum[32];
    int t = threadIdx.x;  // 1024
    int v = (t < nb) ? g_bsum[t] : 0;
    int lane = t & 31, w = t >> 5;
    int incl = v;
    #pragma unroll
    for (int d = 1; d < 32; d <<= 1) {
        int n = __shfl_up_sync(0xFFFFFFFFu, incl, d);
        if (lane >= d) incl += n;
    }
    if (lane == 31) wsum[w] = incl;
    __syncthreads();
    if (w == 0) {
        int s = wsum[lane];
        #pragma unroll
        for (int d = 1; d < 32; d <<= 1) {
            int n = __shfl_up_sync(0xFFFFFFFFu, s, d);
            if (lane >= d) s += n;
        }
        wsum[lane] = s;
    }
    __syncthreads();
    int excl = incl - v + (w ? wsum[w - 1] : 0);
    if (t < nb) g_bsum[t] = excl;
}

__global__ void scan_c_kernel(int N) {
    __shared__ int ws[8];
    int i = blockIdx.x * SCAN_BLK + threadIdx.x;
    int v = (i < N) ? g_off[i] : 0;
    int lane = threadIdx.x & 31, w = threadIdx.x >> 5;
    int incl = v;
    #pragma unroll
    for (int d = 1; d < 32; d <<= 1) {
        int n = __shfl_up_sync(0xFFFFFFFFu, incl, d);
        if (lane >= d) incl += n;
    }
    if (lane == 31) ws[w] = incl;
    __syncthreads();
    if (w == 0 && lane < 8) {
        int s = ws[lane];
        #pragma unroll
        for (int d = 1; d < 8; d <<= 1) {
            int n = __shfl_up_sync(0x000000FFu, s, d);
            if (lane >= d) s += n;
        }
        ws[lane] = s;
    }
    __syncthreads();
    int excl = incl - v + (w ? ws[w - 1] : 0);
    if (i < N) g_off[i] = g_bsum[blockIdx.x] + excl;
}

__global__ void scatter_kernel(const int* __restrict__ src,
                               const int* __restrict__ dst,
                               const float* __restrict__ val, int E) {
    int i = (blockIdx.x * blockDim.x + threadIdx.x) * 4;
    if (i + 4 <= E) {
        int4   s = *(const int4*)(src + i);
        int4   d = *(const int4*)(dst + i);
        float4 v = *(const float4*)(val + i);
        int p0 = atomicAdd(&g_off[d.x], 1);
        int p1 = atomicAdd(&g_off[d.y], 1);
        int p2 = atomicAdd(&g_off[d.z], 1);
        int p3 = atomicAdd(&g_off[d.w], 1);
        g_csr[p0] = make_int2(s.x, __float_as_int(v.x));
        g_csr[p1] = make_int2(s.y, __float_as_int(v.y));
        g_csr[p2] = make_int2(s.z, __float_as_int(v.z));
        g_csr[p3] = make_int2(s.w, __float_as_int(v.w));
    } else {
        for (int j = i; j < E; j++) {
            int p = atomicAdd(&g_off[dst[j]], 1);
            g_csr[p] = make_int2(src[j], __float_as_int(val[j]));
        }
    }
}

// ---------------------------------------------------------------- GEMM1 (wmma tf32)
// support1[N,64] = x[N,256] @ W1[256,64]. R7 version: 4 warps/CTA, 32
// rows/warp, padded smem strides, RNA tf32 conversion via registers.
__global__ void __launch_bounds__(128, 3)
gemm1_wmma_kernel(const float* __restrict__ x, const float* __restrict__ W1,
                  int N) {
    __shared__ float As[128 * ALDM];   // 18KB
    __shared__ float Bs[32 * BLDM];    // 8.5KB

    int tid = threadIdx.x, wid = tid >> 5;
    int m0 = blockIdx.x * 128;

    wmma::fragment<wmma::accumulator, 16, 16, 8, float> acc[2][4];
    #pragma unroll
    for (int i = 0; i < 2; i++)
        #pragma unroll
        for (int nt = 0; nt < 4; nt++) wmma::fill_fragment(acc[i][nt], 0.0f);

    for (int k0 = 0; k0 < 256; k0 += 32) {
        #pragma unroll
        for (int j = 0; j < 8; j++) {
            int i = tid + (j << 7);            // float4 index
            int row = i >> 3;
            int c4 = (i & 7) << 2;
            int gr = m0 + row;
            float4 v = make_float4(0.f, 0.f, 0.f, 0.f);
            if (gr < N)
                v = *(const float4*)(x + (size_t)gr * 256 + k0 + c4);
            float4 t = make_float4(cvt_tf32f(v.x), cvt_tf32f(v.y),
                                   cvt_tf32f(v.z), cvt_tf32f(v.w));
            *(float4*)&As[row * ALDM + c4] = t;
        }
        #pragma unroll
        for (int j = 0; j < 4; j++) {
            int i = tid + (j << 7);
            int row = i >> 4;
            int c4 = (i & 15) << 2;
            float4 v = *(const float4*)(W1 + (size_t)(k0 + row) * 64 + c4);
            float4 t = make_float4(cvt_tf32f(v.x), cvt_tf32f(v.y),
                                   cvt_tf32f(v.z), cvt_tf32f(v.w));
            *(float4*)&Bs[row * BLDM + c4] = t;
        }
        __syncthreads();

        #pragma unroll
        for (int kk = 0; kk < 4; kk++) {
            wmma::fragment<wmma::matrix_a, 16, 16, 8, wmma::precision::tf32,
                           wmma::row_major> a0, a1;
            wmma::load_matrix_sync(a0, &As[(wid * 32) * ALDM + kk * 8], ALDM);
            wmma::load_matrix_sync(a1, &As[(wid * 32 + 16) * ALDM + kk * 8], ALDM);
            #pragma unroll
            for (int nt = 0; nt < 4; nt++) {
                wmma::fragment<wmma::matrix_b, 16, 16, 8, wmma::precision::tf32,
                               wmma::row_major> b_frag;
                wmma::load_matrix_sync(b_frag, &Bs[(kk * 8) * BLDM + nt * 16], BLDM);
                wmma::mma_sync(acc[0][nt], a0, b_frag, acc[0][nt]);
                wmma::mma_sync(acc[1][nt], a1, b_frag, acc[1][nt]);
            }
        }
        __syncthreads();
    }

    #pragma unroll
    for (int i = 0; i < 2; i++) {
        int r0 = m0 + wid * 32 + i * 16;
        #pragma unroll
        for (int nt = 0; nt < 4; nt++)
            wmma::store_matrix_sync(&g_support1[(size_t)r0 * 64 + nt * 16],
                                    acc[i][nt], 64, wmma::mem_row_major);
    }
}

// ---------------------------------------- spMM1 + (relu,b1) + GEMM2 fused
__global__ void spmm1_gemm2_kernel(const float* __restrict__ b1,
                                   const float* __restrict__ W2, int N) {
    __shared__ float w2t[16][68];   // transposed W2, padded
    int tid = threadIdx.x;          // 256
    for (int i = tid; i < 64 * 16; i += 256) {
        int k = i >> 4, j = i & 15;
        w2t[j][k] = W2[i];
    }
    __syncthreads();

    int t = blockIdx.x * 256 + tid;
    int node = t >> 4;
    int c = (t & 15) << 2;
    bool valid = (node < N);

    float4 acc = make_float4(0.f, 0.f, 0.f, 0.f);
    if (valid) {
        int start = node ? g_off[node - 1] : 0;
        int end = g_off[node];
        int e = start;
        for (; e + 4 <= end; e += 4) {
            int2 e0 = g_csr[e], e1 = g_csr[e + 1], e2 = g_csr[e + 2], e3 = g_csr[e + 3];
            float4 v0 = *(const float4*)&g_support1[(size_t)e0.x * 64 + c];
            float4 v1 = *(const float4*)&g_support1[(size_t)e1.x * 64 + c];
            float4 v2 = *(const float4*)&g_support1[(size_t)e2.x * 64 + c];
            float4 v3 = *(const float4*)&g_support1[(size_t)e3.x * 64 + c];
            float w0 = __int_as_float(e0.y), w1 = __int_as_float(e1.y);
            float w2 = __int_as_float(e2.y), w3 = __int_as_float(e3.y);
            acc.x = fmaf(w0, v0.x, acc.x); acc.y = fmaf(w0, v0.y, acc.y);
            acc.z = fmaf(w0, v0.z, acc.z); acc.w = fmaf(w0, v0.w, acc.w);
            acc.x = fmaf(w1, v1.x, acc.x); acc.y = fmaf(w1, v1.y, acc.y);
            acc.z = fmaf(w1, v1.z, acc.z); acc.w = fmaf(w1, v1.w, acc.w);
            acc.x = fmaf(w2, v2.x, acc.x); acc.y = fmaf(w2, v2.y, acc.y);
            acc.z = fmaf(w2, v2.z, acc.z); acc.w = fmaf(w2, v2.w, acc.w);
            acc.x = fmaf(w3, v3.x, acc.x); acc.y = fmaf(w3, v3.y, acc.y);
            acc.z = fmaf(w3, v3.z, acc.z); acc.w = fmaf(w3, v3.w, acc.w);
        }
        for (; e < end; e++) {
            int2 ed = g_csr[e];
            float w = __int_as_float(ed.y);
            float4 v = *(const float4*)&g_support1[(size_t)ed.x * 64 + c];
            acc.x = fmaf(w, v.x, acc.x); acc.y = fmaf(w, v.y, acc.y);
            acc.z = fmaf(w, v.z, acc.z); acc.w = fmaf(w, v.w, acc.w);
        }
        float4 bb = *(const float4*)&b1[c];
        acc.x = fmaxf(acc.x + bb.x, 0.f);
        acc.y = fmaxf(acc.y + bb.y, 0.f);
        acc.z = fmaxf(acc.z + bb.z, 0.f);
        acc.w = fmaxf(acc.w + bb.w, 0.f);
    }

    float part[16];
    #pragma unroll
    for (int j = 0; j < 16; j++) {
        float s = acc.x * w2t[j][c];
        s = fmaf(acc.y, w2t[j][c + 1], s);
        s = fmaf(acc.z, w2t[j][c + 2], s);
        s = fmaf(acc.w, w2t[j][c + 3], s);
        part[j] = s;
    }
    #pragma unroll
    for (int d = 1; d < 16; d <<= 1) {
        #pragma unroll
        for (int j = 0; j < 16; j++)
            part[j] += __shfl_xor_sync(0xFFFFFFFFu, part[j], d);
    }
    int sub = t & 15;
    if (valid && sub < 4) {
        *(float4*)&g_support2[(size_t)node * 16 + sub * 4] =
            make_float4(part[sub * 4], part[sub * 4 + 1],
                        part[sub * 4 + 2], part[sub * 4 + 3]);
    }
}

// ------------------------------------------------ spMM2 + log_softmax fused
__global__ void spmm2_kernel(const float* __restrict__ b2,
                             float* __restrict__ out, int N) {
    int t = blockIdx.x * blockDim.x + threadIdx.x;
    int node = t >> 2;
    int q = (t & 3) << 2;

    float4 acc = make_float4(0.f, 0.f, 0.f, 0.f);
    if (node < N) {
        int start = node ? g_off[node - 1] : 0;
        int end = g_off[node];
        int e = start;
        for (; e + 4 <= end; e += 4) {
            int2 e0 = g_csr[e], e1 = g_csr[e + 1], e2 = g_csr[e + 2], e3 = g_csr[e + 3];
            float4 v0 = *(const float4*)&g_support2[(size_t)e0.x * 16 + q];
            float4 v1 = *(const float4*)&g_support2[(size_t)e1.x * 16 + q];
            float4 v2 = *(const float4*)&g_support2[(size_t)e2.x * 16 + q];
            float4 v3 = *(const float4*)&g_support2[(size_t)e3.x * 16 + q];
            float w0 = __int_as_float(e0.y), w1 = __int_as_float(e1.y);
            float w2 = __int_as_float(e2.y), w3 = __int_as_float(e3.y);
            acc.x = fmaf(w0, v0.x, acc.x); acc.y = fmaf(w0, v0.y, acc.y);
            acc.z = fmaf(w0, v0.z, acc.z); acc.w = fmaf(w0, v0.w, acc.w);
            acc.x = fmaf(w1, v1.x, acc.x); acc.y = fmaf(w1, v1.y, acc.y);
            acc.z = fmaf(w1, v1.z, acc.z); acc.w = fmaf(w1, v1.w, acc.w);
            acc.x = fmaf(w2, v2.x, acc.x); acc.y = fmaf(w2, v2.y, acc.y);
            acc.z = fmaf(w2, v2.z, acc.z); acc.w = fmaf(w2, v2.w, acc.w);
            acc.x = fmaf(w3, v3.x, acc.x); acc.y = fmaf(w3, v3.y, acc.y);
            acc.z = fmaf(w3, v3.z, acc.z); acc.w = fmaf(w3, v3.w, acc.w);
        }
        for (; e < end; e++) {
            int2 ed = g_csr[e];
            float w = __int_as_float(ed.y);
            float4 v = *(const float4*)&g_support2[(size_t)ed.x * 16 + q];
            acc.x = fmaf(w, v.x, acc.x); acc.y = fmaf(w, v.y, acc.y);
            acc.z = fmaf(w, v.z, acc.z); acc.w = fmaf(w, v.w, acc.w);
        }
        float4 bb = *(const float4*)&b2[q];
        acc.x += bb.x; acc.y += bb.y; acc.z += bb.z; acc.w += bb.w;
    }

    float m = fmaxf(fmaxf(acc.x, acc.y), fmaxf(acc.z, acc.w));
    m = fmaxf(m, __shfl_xor_sync(0xFFFFFFFFu, m, 1));
    m = fmaxf(m, __shfl_xor_sync(0xFFFFFFFFu, m, 2));
    float s = expf(acc.x - m) + expf(acc.y - m) + expf(acc.z - m) + expf(acc.w - m);
    s += __shfl_xor_sync(0xFFFFFFFFu, s, 1);
    s += __shfl_xor_sync(0xFFFFFFFFu, s, 2);
    float lse = m + logf(s);

    if (node < N) {
        *(float4*)&out[(size_t)node * 16 + q] =
            make_float4(acc.x - lse, acc.y - lse, acc.z - lse, acc.w - lse);
    }
}

// ---------------------------------------------------------------- launch
extern "C" void kernel_launch(void* const* d_in, const int* in_sizes, int n_in,
                              void* d_out, int out_size) {
    const float* x    = (const float*)d_in[0];
    const int*   esrc = (const int*)d_in[1];
    const int*   edst = (const int*)d_in[2];
    const float* ev   = (const float*)d_in[3];
    const float* W1   = (const float*)d_in[4];
    const float* b1   = (const float*)d_in[5];
    const float* W2   = (const float*)d_in[6];
    const float* b2   = (const float*)d_in[7];
    float* out = (float*)d_out;

    int E = in_sizes[1];
    int N = in_sizes[0] / 256;

    int eq = (E + 3) / 4;
    int nq = (N + 3) / 4;
    int nb = (N + SCAN_BLK - 1) / SCAN_BLK;

    // Side stream + events, created once on the first (uncaptured)
    // correctness call; replayed identically under graph capture.
    // (No device memory is allocated; work per call is identical.)
    static cudaStream_t s2 = nullptr;
    static cudaEvent_t evFork = nullptr, evJoin = nullptr;
    if (!s2) {
        cudaStreamCreateWithFlags(&s2, cudaStreamNonBlocking);
        cudaEventCreateWithFlags(&evFork, cudaEventDisableTiming);
        cudaEventCreateWithFlags(&evJoin, cudaEventDisableTiming);
    }

    // Fork: CSR build on s2, gemm1 on the main (capture) stream.
    cudaEventRecord(evFork, 0);
    cudaStreamWaitEvent(s2, evFork, 0);

    zero_off_kernel<<<(nq + 255) / 256, 256, 0, s2>>>(N);
    hist_kernel<<<(eq + 255) / 256, 256, 0, s2>>>(edst, E);
    scan_a_kernel<<<nb, SCAN_BLK, 0, s2>>>(N);
    scan_b_kernel<<<1, 1024, 0, s2>>>(nb);
    scan_c_kernel<<<nb, SCAN_BLK, 0, s2>>>(N);
    scatter_kernel<<<(eq + 255) / 256, 256, 0, s2>>>(esrc, edst, ev, E);
    cudaEventRecord(evJoin, s2);

    gemm1_wmma_kernel<<<(N + 127) / 128, 128>>>(x, W1, N);

    // Join: spMM needs both gemm1 (program order) and the CSR (event).
    cudaStreamWaitEvent(0, evJoin, 0);

    spmm1_gemm2_kernel<<<(N * 16 + 255) / 256, 256>>>(b1, W2, N);
    spmm2_kernel<<<(N * 4 + 255) / 256, 256>>>(b2, out, N);
}